// round 5
// baseline (speedup 1.0000x reference)
#include <cuda_runtime.h>
#include <cuda_bf16.h>
#include <cstdint>

typedef unsigned long long ull;

// ---------------- f32x2 packed helpers (Blackwell) ----------------
__device__ __forceinline__ ull ffma2(ull a, ull b, ull c) {
    ull d;
    asm("fma.rn.f32x2 %0, %1, %2, %3;" : "=l"(d) : "l"(a), "l"(b), "l"(c));
    return d;
}
__device__ __forceinline__ ull pack2(float lo, float hi) {
    ull r;
    asm("mov.b64 %0, {%1, %2};" : "=l"(r) : "f"(lo), "f"(hi));
    return r;
}
__device__ __forceinline__ void unpack2(ull v, float& lo, float& hi) {
    asm("mov.b64 {%0, %1}, %2;" : "=f"(lo), "=f"(hi) : "l"(v));
}
__device__ __forceinline__ ull relu2(ull v) {
    float lo, hi;
    unpack2(v, lo, hi);
    return pack2(fmaxf(lo, 0.0f), fmaxf(hi, 0.0f));
}

static constexpr int C = 16;
static constexpr int TPB = 256;

// 4 rows per thread (two f32x2 row-pairs). Register-pressure-shaped:
//  - GEMM1 consumes input chunks as h accumulators come alive (peak ~120)
//  - GEMM2 streams 4-output chunks straight to STG.128 (no o[] array)
__global__ __launch_bounds__(TPB, 2)
void dmasif_fused_kernel(const float* __restrict__ feat,
                         float* __restrict__ out,
                         const float* __restrict__ Wt,
                         const float* __restrict__ bt,
                         const float* __restrict__ Wa,
                         const float* __restrict__ ba,
                         const float* __restrict__ Wb,
                         const float* __restrict__ bb,
                         long long n)
{
    __shared__ ull sWc[C * C];   // folded Wc = Wa @ Wt, [o*16+i], (w,w) packed
    __shared__ ull sWb[C * C];   // Wb, [q*16+o], (w,w) packed
    __shared__ ull sbc[C];
    __shared__ ull sbb[C];

    const int t = threadIdx.x;
    {
        const int o = t >> 4;
        const int i = t & 15;
        float acc = 0.0f;
#pragma unroll
        for (int m = 0; m < C; m++)
            acc += Wa[o * C + m] * Wt[m * C + i];
        sWc[t] = pack2(acc, acc);
        const float wb = Wb[t];
        sWb[t] = pack2(wb, wb);
        if (t < C) {
            float b = ba[t];
#pragma unroll
            for (int m = 0; m < C; m++)
                b += Wa[t * C + m] * bt[m];
            sbc[t] = pack2(b, b);
            const float b2 = bb[t];
            sbb[t] = pack2(b2, b2);
        }
    }
    __syncthreads();

    const long long base = ((long long)blockIdx.x * TPB + t) * 4;
    if (base >= n) return;
    const bool full = (base + 4 <= n);

    // ---- load 4 rows of features, pack into two row-pairs ----
    ull p0[C], p1[C];
    if (full) {
        const float4* f4 = reinterpret_cast<const float4*>(feat + base * C);
        float4 ra[4], rb[4], rc[4], rd[4];
#pragma unroll
        for (int j = 0; j < 4; j++) {
            ra[j] = f4[0 * 4 + j];
            rb[j] = f4[1 * 4 + j];
            rc[j] = f4[2 * 4 + j];
            rd[j] = f4[3 * 4 + j];
        }
#pragma unroll
        for (int j = 0; j < 4; j++) {
            p0[4 * j + 0] = pack2(ra[j].x, rb[j].x);
            p0[4 * j + 1] = pack2(ra[j].y, rb[j].y);
            p0[4 * j + 2] = pack2(ra[j].z, rb[j].z);
            p0[4 * j + 3] = pack2(ra[j].w, rb[j].w);
            p1[4 * j + 0] = pack2(rc[j].x, rd[j].x);
            p1[4 * j + 1] = pack2(rc[j].y, rd[j].y);
            p1[4 * j + 2] = pack2(rc[j].z, rd[j].z);
            p1[4 * j + 3] = pack2(rc[j].w, rd[j].w);
        }
    } else {
        float rA[C], rB[C], rC[C], rD[C];
#pragma unroll
        for (int i = 0; i < C; i++) { rA[i] = 0.f; rB[i] = 0.f; rC[i] = 0.f; rD[i] = 0.f; }
        if (base + 0 < n) { for (int i = 0; i < C; i++) rA[i] = feat[(base + 0) * C + i]; }
        if (base + 1 < n) { for (int i = 0; i < C; i++) rB[i] = feat[(base + 1) * C + i]; }
        if (base + 2 < n) { for (int i = 0; i < C; i++) rC[i] = feat[(base + 2) * C + i]; }
        if (base + 3 < n) { for (int i = 0; i < C; i++) rD[i] = feat[(base + 3) * C + i]; }
#pragma unroll
        for (int i = 0; i < C; i++) {
            p0[i] = pack2(rA[i], rB[i]);
            p1[i] = pack2(rC[i], rD[i]);
        }
    }

    // ---- GEMM1 + ReLU: h = relu(f @ Wc^T + bc), i-chunked so p dies as h fills ----
    ull h0[C], h1[C];
#pragma unroll
    for (int o = 0; o < C; o++) {
        ull a0 = sbc[o];
        ull a1 = a0;
#pragma unroll
        for (int ii = 0; ii < 4; ii++) {
            const ull w = sWc[o * C + ii];
            a0 = ffma2(p0[ii], w, a0);
            a1 = ffma2(p1[ii], w, a1);
        }
        h0[o] = a0;
        h1[o] = a1;
    }
#pragma unroll
    for (int ic = 1; ic < 4; ic++) {
#pragma unroll
        for (int o = 0; o < C; o++) {
            ull a0 = h0[o];
            ull a1 = h1[o];
#pragma unroll
            for (int ii = 0; ii < 4; ii++) {
                const int i = 4 * ic + ii;
                const ull w = sWc[o * C + i];
                a0 = ffma2(p0[i], w, a0);
                a1 = ffma2(p1[i], w, a1);
            }
            h0[o] = a0;
            h1[o] = a1;
        }
    }
#pragma unroll
    for (int o = 0; o < C; o++) {
        h0[o] = relu2(h0[o]);
        h1[o] = relu2(h1[o]);
    }

    // ---- GEMM2: out = h @ Wb^T + bb, streamed 4-output chunks -> STG.128 ----
    float4* g4 = reinterpret_cast<float4*>(out + base * C);
#pragma unroll
    for (int qc = 0; qc < 4; qc++) {
        float vA[4], vB[4], vC[4], vD[4];
#pragma unroll
        for (int qq = 0; qq < 4; qq++) {
            const int q = 4 * qc + qq;
            ull a0 = sbb[q];
            ull a1 = a0;
#pragma unroll
            for (int o = 0; o < C; o++) {
                const ull w = sWb[q * C + o];
                a0 = ffma2(h0[o], w, a0);
                a1 = ffma2(h1[o], w, a1);
            }
            unpack2(a0, vA[qq], vB[qq]);
            unpack2(a1, vC[qq], vD[qq]);
        }
        if (full) {
            g4[0 * 4 + qc] = make_float4(vA[0], vA[1], vA[2], vA[3]);
            g4[1 * 4 + qc] = make_float4(vB[0], vB[1], vB[2], vB[3]);
            g4[2 * 4 + qc] = make_float4(vC[0], vC[1], vC[2], vC[3]);
            g4[3 * 4 + qc] = make_float4(vD[0], vD[1], vD[2], vD[3]);
        } else {
#pragma unroll
            for (int qq = 0; qq < 4; qq++) {
                const int q = 4 * qc + qq;
                if (base + 0 < n) out[(base + 0) * C + q] = vA[qq];
                if (base + 1 < n) out[(base + 1) * C + q] = vB[qq];
                if (base + 2 < n) out[(base + 2) * C + q] = vC[qq];
                if (base + 3 < n) out[(base + 3) * C + q] = vD[qq];
            }
        }
    }
}

extern "C" void kernel_launch(void* const* d_in, const int* in_sizes, int n_in,
                              void* d_out, int out_size)
{
    // metadata order: features, points, nuv, Wt, bt, Wa, ba, Wb, bb, ranges
    const float* feat = (const float*)d_in[0];
    const float* Wt   = (const float*)d_in[3];
    const float* bt   = (const float*)d_in[4];
    const float* Wa   = (const float*)d_in[5];
    const float* ba   = (const float*)d_in[6];
    const float* Wb   = (const float*)d_in[7];
    const float* bb   = (const float*)d_in[8];
    float* out = (float*)d_out;

    const long long n = (long long)in_sizes[0] / C;
    const long long quads = (n + 3) / 4;
    const int blocks = (int)((quads + TPB - 1) / TPB);

    dmasif_fused_kernel<<<blocks, TPB>>>(feat, out, Wt, bt, Wa, ba, Wb, bb, n);
}

// round 6
// speedup vs baseline: 1.0317x; 1.0317x over previous
#include <cuda_runtime.h>
#include <cuda_bf16.h>
#include <cstdint>

typedef unsigned long long ull;

// ---------------- f32x2 packed helpers (Blackwell) ----------------
__device__ __forceinline__ ull ffma2(ull a, ull b, ull c) {
    ull d;
    asm("fma.rn.f32x2 %0, %1, %2, %3;" : "=l"(d) : "l"(a), "l"(b), "l"(c));
    return d;
}
__device__ __forceinline__ ull pack2(float lo, float hi) {
    ull r;
    asm("mov.b64 %0, {%1, %2};" : "=l"(r) : "f"(lo), "f"(hi));
    return r;
}
__device__ __forceinline__ void unpack2(ull v, float& lo, float& hi) {
    asm("mov.b64 {%0, %1}, %2;" : "=f"(lo), "=f"(hi) : "l"(v));
}
__device__ __forceinline__ ull relu2(ull v) {
    float lo, hi;
    unpack2(v, lo, hi);
    return pack2(fmaxf(lo, 0.0f), fmaxf(hi, 0.0f));
}

static constexpr int C = 16;
static constexpr int TPB = 256;

// 4 rows per thread (two f32x2 row-pairs).
// Weight reads vectorized: (w,w)-packed pairs fetched 2-at-a-time via LDS.128
// (ulonglong2) -> halves LDS instruction count vs LDS.64 per weight.
__global__ __launch_bounds__(TPB, 2)
void dmasif_fused_kernel(const float* __restrict__ feat,
                         float* __restrict__ out,
                         const float* __restrict__ Wt,
                         const float* __restrict__ bt,
                         const float* __restrict__ Wa,
                         const float* __restrict__ ba,
                         const float* __restrict__ Wb,
                         const float* __restrict__ bb,
                         long long n)
{
    __shared__ __align__(16) ull sWc[C * C];   // folded Wc = Wa @ Wt, [o*16+i], (w,w)
    __shared__ __align__(16) ull sWb[C * C];   // Wb, [q*16+o], (w,w)
    __shared__ ull sbc[C];
    __shared__ ull sbb[C];

    const int t = threadIdx.x;
    {
        const int o = t >> 4;
        const int i = t & 15;
        float acc = 0.0f;
#pragma unroll
        for (int m = 0; m < C; m++)
            acc += Wa[o * C + m] * Wt[m * C + i];
        sWc[t] = pack2(acc, acc);
        const float wb = Wb[t];
        sWb[t] = pack2(wb, wb);
        if (t < C) {
            float b = ba[t];
#pragma unroll
            for (int m = 0; m < C; m++)
                b += Wa[t * C + m] * bt[m];
            sbc[t] = pack2(b, b);
            const float b2 = bb[t];
            sbb[t] = pack2(b2, b2);
        }
    }
    __syncthreads();

    const ulonglong2* __restrict__ wc2 = reinterpret_cast<const ulonglong2*>(sWc);
    const ulonglong2* __restrict__ wb2 = reinterpret_cast<const ulonglong2*>(sWb);

    const long long base = ((long long)blockIdx.x * TPB + t) * 4;
    if (base >= n) return;
    const bool full = (base + 4 <= n);

    // ---- load 4 rows of features, pack into two row-pairs ----
    ull p0[C], p1[C];
    if (full) {
        const float4* f4 = reinterpret_cast<const float4*>(feat + base * C);
        float4 ra[4], rb[4], rc[4], rd[4];
#pragma unroll
        for (int j = 0; j < 4; j++) {
            ra[j] = f4[0 * 4 + j];
            rb[j] = f4[1 * 4 + j];
            rc[j] = f4[2 * 4 + j];
            rd[j] = f4[3 * 4 + j];
        }
#pragma unroll
        for (int j = 0; j < 4; j++) {
            p0[4 * j + 0] = pack2(ra[j].x, rb[j].x);
            p0[4 * j + 1] = pack2(ra[j].y, rb[j].y);
            p0[4 * j + 2] = pack2(ra[j].z, rb[j].z);
            p0[4 * j + 3] = pack2(ra[j].w, rb[j].w);
            p1[4 * j + 0] = pack2(rc[j].x, rd[j].x);
            p1[4 * j + 1] = pack2(rc[j].y, rd[j].y);
            p1[4 * j + 2] = pack2(rc[j].z, rd[j].z);
            p1[4 * j + 3] = pack2(rc[j].w, rd[j].w);
        }
    } else {
        float rA[C], rB[C], rC[C], rD[C];
#pragma unroll
        for (int i = 0; i < C; i++) { rA[i] = 0.f; rB[i] = 0.f; rC[i] = 0.f; rD[i] = 0.f; }
        if (base + 0 < n) { for (int i = 0; i < C; i++) rA[i] = feat[(base + 0) * C + i]; }
        if (base + 1 < n) { for (int i = 0; i < C; i++) rB[i] = feat[(base + 1) * C + i]; }
        if (base + 2 < n) { for (int i = 0; i < C; i++) rC[i] = feat[(base + 2) * C + i]; }
        if (base + 3 < n) { for (int i = 0; i < C; i++) rD[i] = feat[(base + 3) * C + i]; }
#pragma unroll
        for (int i = 0; i < C; i++) {
            p0[i] = pack2(rA[i], rB[i]);
            p1[i] = pack2(rC[i], rD[i]);
        }
    }

    // ---- GEMM1 + ReLU: h = relu(f @ Wc^T + bc), i-chunked; vector LDS.128 weights ----
    ull h0[C], h1[C];
#pragma unroll
    for (int o = 0; o < C; o++) {
        ull a0 = sbc[o];
        ull a1 = a0;
        const ulonglong2 wA = wc2[o * 8 + 0];   // weights i=0,1
        const ulonglong2 wB = wc2[o * 8 + 1];   // weights i=2,3
        a0 = ffma2(p0[0], wA.x, a0);  a1 = ffma2(p1[0], wA.x, a1);
        a0 = ffma2(p0[1], wA.y, a0);  a1 = ffma2(p1[1], wA.y, a1);
        a0 = ffma2(p0[2], wB.x, a0);  a1 = ffma2(p1[2], wB.x, a1);
        a0 = ffma2(p0[3], wB.y, a0);  a1 = ffma2(p1[3], wB.y, a1);
        h0[o] = a0;
        h1[o] = a1;
    }
#pragma unroll
    for (int ic = 1; ic < 4; ic++) {
#pragma unroll
        for (int o = 0; o < C; o++) {
            ull a0 = h0[o];
            ull a1 = h1[o];
            const int i = 4 * ic;
            const ulonglong2 wA = wc2[o * 8 + 2 * ic + 0];
            const ulonglong2 wB = wc2[o * 8 + 2 * ic + 1];
            a0 = ffma2(p0[i + 0], wA.x, a0);  a1 = ffma2(p1[i + 0], wA.x, a1);
            a0 = ffma2(p0[i + 1], wA.y, a0);  a1 = ffma2(p1[i + 1], wA.y, a1);
            a0 = ffma2(p0[i + 2], wB.x, a0);  a1 = ffma2(p1[i + 2], wB.x, a1);
            a0 = ffma2(p0[i + 3], wB.y, a0);  a1 = ffma2(p1[i + 3], wB.y, a1);
            h0[o] = a0;
            h1[o] = a1;
        }
    }
#pragma unroll
    for (int o = 0; o < C; o++) {
        h0[o] = relu2(h0[o]);
        h1[o] = relu2(h1[o]);
    }

    // ---- GEMM2: out = h @ Wb^T + bb, streamed 4-output chunks -> STG.128 ----
    float4* g4 = reinterpret_cast<float4*>(out + base * C);
#pragma unroll
    for (int qc = 0; qc < 4; qc++) {
        float vA[4], vB[4], vC[4], vD[4];
#pragma unroll
        for (int qq = 0; qq < 4; qq++) {
            const int q = 4 * qc + qq;
            ull a0 = sbb[q];
            ull a1 = a0;
#pragma unroll
            for (int oc = 0; oc < 8; oc++) {
                const ulonglong2 w = wb2[q * 8 + oc];
                const int o = 2 * oc;
                a0 = ffma2(h0[o + 0], w.x, a0);  a1 = ffma2(h1[o + 0], w.x, a1);
                a0 = ffma2(h0[o + 1], w.y, a0);  a1 = ffma2(h1[o + 1], w.y, a1);
            }
            unpack2(a0, vA[qq], vB[qq]);
            unpack2(a1, vC[qq], vD[qq]);
        }
        if (full) {
            g4[0 * 4 + qc] = make_float4(vA[0], vA[1], vA[2], vA[3]);
            g4[1 * 4 + qc] = make_float4(vB[0], vB[1], vB[2], vB[3]);
            g4[2 * 4 + qc] = make_float4(vC[0], vC[1], vC[2], vC[3]);
            g4[3 * 4 + qc] = make_float4(vD[0], vD[1], vD[2], vD[3]);
        } else {
#pragma unroll
            for (int qq = 0; qq < 4; qq++) {
                const int q = 4 * qc + qq;
                if (base + 0 < n) out[(base + 0) * C + q] = vA[qq];
                if (base + 1 < n) out[(base + 1) * C + q] = vB[qq];
                if (base + 2 < n) out[(base + 2) * C + q] = vC[qq];
                if (base + 3 < n) out[(base + 3) * C + q] = vD[qq];
            }
        }
    }
}

extern "C" void kernel_launch(void* const* d_in, const int* in_sizes, int n_in,
                              void* d_out, int out_size)
{
    // metadata order: features, points, nuv, Wt, bt, Wa, ba, Wb, bb, ranges
    const float* feat = (const float*)d_in[0];
    const float* Wt   = (const float*)d_in[3];
    const float* bt   = (const float*)d_in[4];
    const float* Wa   = (const float*)d_in[5];
    const float* ba   = (const float*)d_in[6];
    const float* Wb   = (const float*)d_in[7];
    const float* bb   = (const float*)d_in[8];
    float* out = (float*)d_out;

    const long long n = (long long)in_sizes[0] / C;
    const long long quads = (n + 3) / 4;
    const int blocks = (int)((quads + TPB - 1) / TPB);

    dmasif_fused_kernel<<<blocks, TPB>>>(feat, out, Wt, bt, Wa, ba, Wb, bb, n);
}

// round 9
// speedup vs baseline: 1.2200x; 1.1825x over previous
#include <cuda_runtime.h>
#include <cuda_bf16.h>
#include <cstdint>

typedef unsigned long long ull;

// ---------------- f32x2 packed helpers (Blackwell) ----------------
__device__ __forceinline__ ull ffma2(ull a, ull b, ull c) {
    ull d;
    asm("fma.rn.f32x2 %0, %1, %2, %3;" : "=l"(d) : "l"(a), "l"(b), "l"(c));
    return d;
}
__device__ __forceinline__ ull pack2(float lo, float hi) {
    ull r;
    asm("mov.b64 %0, {%1, %2};" : "=l"(r) : "f"(lo), "f"(hi));
    return r;
}
__device__ __forceinline__ void unpack2(ull v, float& lo, float& hi) {
    asm("mov.b64 {%0, %1}, %2;" : "=f"(lo), "=f"(hi) : "l"(v));
}
__device__ __forceinline__ ull relu2(ull v) {
    float lo, hi;
    unpack2(v, lo, hi);
    return pack2(fmaxf(lo, 0.0f), fmaxf(hi, 0.0f));
}

static constexpr int C = 16;
static constexpr int TPB = 256;

// Dual f32x2 pairing: weight-pairs in the vector lanes (scalar smem weights,
// transposed so channels are contiguous -> LDS.128 = 4 distinct weights =
// 2 ffma2 operands), features/h duplicated (f,f) via 1 ALU pack each.
// Halves weight smem bytes per thread: 4KB -> 2KB.
__global__ __launch_bounds__(TPB, 2)
void dmasif_fused_kernel(const float* __restrict__ feat,
                         float* __restrict__ out,
                         const float* __restrict__ Wt,
                         const float* __restrict__ bt,
                         const float* __restrict__ Wa,
                         const float* __restrict__ ba,
                         const float* __restrict__ Wb,
                         const float* __restrict__ bb,
                         long long n)
{
    __shared__ __align__(16) float sWcT[C * C];  // [i*16 + o]  folded Wc^T (scalar)
    __shared__ __align__(16) float sWbT[C * C];  // [o*16 + q]  Wb^T (scalar)
    __shared__ ull sbcP[8];                      // bias pairs (bc[2p], bc[2p+1])
    __shared__ ull sbbP[8];                      // bias pairs (bb[2p], bb[2p+1])

    const int t = threadIdx.x;
    {
        const int o = t & 15;
        const int i = t >> 4;
        float acc = 0.0f;
#pragma unroll
        for (int m = 0; m < C; m++)
            acc += Wa[o * C + m] * Wt[m * C + i];
        sWcT[i * C + o] = acc;                       // transposed: o contiguous
        sWbT[t] = Wb[(t & 15) * C + (t >> 4)];       // sWbT[o*16+q] = Wb[q][o]
        if (t < 8) {
            float b0 = ba[2 * t + 0], b1 = ba[2 * t + 1];
#pragma unroll
            for (int m = 0; m < C; m++) {
                b0 += Wa[(2 * t + 0) * C + m] * bt[m];
                b1 += Wa[(2 * t + 1) * C + m] * bt[m];
            }
            sbcP[t] = pack2(b0, b1);
            sbbP[t] = pack2(bb[2 * t + 0], bb[2 * t + 1]);
        }
    }
    __syncthreads();

    const ulonglong2* __restrict__ wc2 = reinterpret_cast<const ulonglong2*>(sWcT);
    const ulonglong2* __restrict__ wb2 = reinterpret_cast<const ulonglong2*>(sWbT);

    const long long base = ((long long)blockIdx.x * TPB + t) * 4;
    if (base >= n) return;

    if (base + 4 > n) {
        // ---- scalar tail path (dead for N%4==0, kept for safety) ----
        for (int r = 0; r < 4; r++) {
            const long long row = base + r;
            if (row >= n) break;
            float h[C];
#pragma unroll
            for (int q = 0; q < C; q++) {
                float blo, bhi;
                unpack2(sbcP[q >> 1], blo, bhi);
                float a = (q & 1) ? bhi : blo;
                for (int i = 0; i < C; i++)
                    a += feat[row * C + i] * sWcT[i * C + q];
                h[q] = fmaxf(a, 0.0f);
            }
#pragma unroll
            for (int q = 0; q < C; q++) {
                float blo, bhi;
                unpack2(sbbP[q >> 1], blo, bhi);
                float a = (q & 1) ? bhi : blo;
                for (int o = 0; o < C; o++)
                    a += h[o] * sWbT[o * C + q];
                out[row * C + q] = a;
            }
        }
        return;
    }

    // ================= main path: 4 full rows =================
    // GEMM1 accumulators: acc[r][p] = (h[r][2p], h[r][2p+1])
    ull acc[4][8];
    {
        ull bp[8];
#pragma unroll
        for (int p = 0; p < 8; p++) bp[p] = sbcP[p];
#pragma unroll
        for (int r = 0; r < 4; r++)
#pragma unroll
            for (int p = 0; p < 8; p++) acc[r][p] = bp[p];
    }

    const float4* f4 = reinterpret_cast<const float4*>(feat + base * C);
#pragma unroll
    for (int ic = 0; ic < 4; ic++) {
        const float4 g0 = f4[0 * 4 + ic];
        const float4 g1 = f4[1 * 4 + ic];
        const float4 g2 = f4[2 * 4 + ic];
        const float4 g3 = f4[3 * 4 + ic];
        float e0v[4] = {g0.x, g0.y, g0.z, g0.w};
        float e1v[4] = {g1.x, g1.y, g1.z, g1.w};
        float e2v[4] = {g2.x, g2.y, g2.z, g2.w};
        float e3v[4] = {g3.x, g3.y, g3.z, g3.w};
#pragma unroll
        for (int ii = 0; ii < 4; ii++) {
            const int i = ic * 4 + ii;
            const ulonglong2 wA = wc2[i * 4 + 0];  // pairs (o0,o1),(o2,o3)
            const ulonglong2 wB = wc2[i * 4 + 1];  // (o4,o5),(o6,o7)
            const ulonglong2 wC = wc2[i * 4 + 2];  // (o8,o9),(o10,o11)
            const ulonglong2 wD = wc2[i * 4 + 3];  // (o12,o13),(o14,o15)
            const ull d0 = pack2(e0v[ii], e0v[ii]);
            const ull d1 = pack2(e1v[ii], e1v[ii]);
            const ull d2 = pack2(e2v[ii], e2v[ii]);
            const ull d3 = pack2(e3v[ii], e3v[ii]);
            acc[0][0] = ffma2(d0, wA.x, acc[0][0]); acc[0][1] = ffma2(d0, wA.y, acc[0][1]);
            acc[0][2] = ffma2(d0, wB.x, acc[0][2]); acc[0][3] = ffma2(d0, wB.y, acc[0][3]);
            acc[0][4] = ffma2(d0, wC.x, acc[0][4]); acc[0][5] = ffma2(d0, wC.y, acc[0][5]);
            acc[0][6] = ffma2(d0, wD.x, acc[0][6]); acc[0][7] = ffma2(d0, wD.y, acc[0][7]);
            acc[1][0] = ffma2(d1, wA.x, acc[1][0]); acc[1][1] = ffma2(d1, wA.y, acc[1][1]);
            acc[1][2] = ffma2(d1, wB.x, acc[1][2]); acc[1][3] = ffma2(d1, wB.y, acc[1][3]);
            acc[1][4] = ffma2(d1, wC.x, acc[1][4]); acc[1][5] = ffma2(d1, wC.y, acc[1][5]);
            acc[1][6] = ffma2(d1, wD.x, acc[1][6]); acc[1][7] = ffma2(d1, wD.y, acc[1][7]);
            acc[2][0] = ffma2(d2, wA.x, acc[2][0]); acc[2][1] = ffma2(d2, wA.y, acc[2][1]);
            acc[2][2] = ffma2(d2, wB.x, acc[2][2]); acc[2][3] = ffma2(d2, wB.y, acc[2][3]);
            acc[2][4] = ffma2(d2, wC.x, acc[2][4]); acc[2][5] = ffma2(d2, wC.y, acc[2][5]);
            acc[2][6] = ffma2(d2, wD.x, acc[2][6]); acc[2][7] = ffma2(d2, wD.y, acc[2][7]);
            acc[3][0] = ffma2(d3, wA.x, acc[3][0]); acc[3][1] = ffma2(d3, wA.y, acc[3][1]);
            acc[3][2] = ffma2(d3, wB.x, acc[3][2]); acc[3][3] = ffma2(d3, wB.y, acc[3][3]);
            acc[3][4] = ffma2(d3, wC.x, acc[3][4]); acc[3][5] = ffma2(d3, wC.y, acc[3][5]);
            acc[3][6] = ffma2(d3, wD.x, acc[3][6]); acc[3][7] = ffma2(d3, wD.y, acc[3][7]);
        }
    }

#pragma unroll
    for (int r = 0; r < 4; r++)
#pragma unroll
        for (int p = 0; p < 8; p++) acc[r][p] = relu2(acc[r][p]);

    // ---- GEMM2 in two q-halves to bound register pressure ----
    float* outp = out + base * C;
#pragma unroll
    for (int half = 0; half < 2; half++) {
        ull a2[4][4];  // q-pairs for this half
        {
            ull bp0 = sbbP[half * 4 + 0], bp1 = sbbP[half * 4 + 1];
            ull bp2 = sbbP[half * 4 + 2], bp3 = sbbP[half * 4 + 3];
#pragma unroll
            for (int r = 0; r < 4; r++) {
                a2[r][0] = bp0; a2[r][1] = bp1; a2[r][2] = bp2; a2[r][3] = bp3;
            }
        }
#pragma unroll
        for (int o = 0; o < C; o++) {
            const ulonglong2 wA = wb2[o * 4 + half * 2 + 0];
            const ulonglong2 wB = wb2[o * 4 + half * 2 + 1];
#pragma unroll
            for (int r = 0; r < 4; r++) {
                float hlo, hhi;
                unpack2(acc[r][o >> 1], hlo, hhi);
                const float hs = (o & 1) ? hhi : hlo;
                const ull hd = pack2(hs, hs);
                a2[r][0] = ffma2(hd, wA.x, a2[r][0]);
                a2[r][1] = ffma2(hd, wA.y, a2[r][1]);
                a2[r][2] = ffma2(hd, wB.x, a2[r][2]);
                a2[r][3] = ffma2(hd, wB.y, a2[r][3]);
            }
        }
        float4* g4 = reinterpret_cast<float4*>(outp + half * 8);
#pragma unroll
        for (int r = 0; r < 4; r++) {
            float v0, v1, v2, v3, v4, v5, v6, v7;
            unpack2(a2[r][0], v0, v1);
            unpack2(a2[r][1], v2, v3);
            unpack2(a2[r][2], v4, v5);
            unpack2(a2[r][3], v6, v7);
            // row r, columns half*8 .. half*8+7  (row stride 16 floats = 4 float4)
            g4[r * 4 + 0] = make_float4(v0, v1, v2, v3);
            g4[r * 4 + 1] = make_float4(v4, v5, v6, v7);
        }
    }
}

extern "C" void kernel_launch(void* const* d_in, const int* in_sizes, int n_in,
                              void* d_out, int out_size)
{
    // metadata order: features, points, nuv, Wt, bt, Wa, ba, Wb, bb, ranges
    const float* feat = (const float*)d_in[0];
    const float* Wt   = (const float*)d_in[3];
    const float* bt   = (const float*)d_in[4];
    const float* Wa   = (const float*)d_in[5];
    const float* ba   = (const float*)d_in[6];
    const float* Wb   = (const float*)d_in[7];
    const float* bb   = (const float*)d_in[8];
    float* out = (float*)d_out;

    const long long n = (long long)in_sizes[0] / C;
    const long long quads = (n + 3) / 4;
    const int blocks = (int)((quads + TPB - 1) / TPB);

    dmasif_fused_kernel<<<blocks, TPB>>>(feat, out, Wt, bt, Wa, ba, Wb, bb, n);
}

// round 10
// speedup vs baseline: 1.4186x; 1.1628x over previous
#include <cuda_runtime.h>
#include <cuda_bf16.h>
#include <cstdint>

typedef unsigned long long ull;

// ---------------- f32x2 packed helpers (Blackwell) ----------------
__device__ __forceinline__ ull ffma2(ull a, ull b, ull c) {
    ull d;
    asm("fma.rn.f32x2 %0, %1, %2, %3;" : "=l"(d) : "l"(a), "l"(b), "l"(c));
    return d;
}
__device__ __forceinline__ ull pack2(float lo, float hi) {
    ull r;
    asm("mov.b64 %0, {%1, %2};" : "=l"(r) : "f"(lo), "f"(hi));
    return r;
}
__device__ __forceinline__ void unpack2(ull v, float& lo, float& hi) {
    asm("mov.b64 {%0, %1}, %2;" : "=f"(lo), "=f"(hi) : "l"(v));
}
__device__ __forceinline__ ull relu2(ull v) {
    float lo, hi;
    unpack2(v, lo, hi);
    return pack2(fmaxf(lo, 0.0f), fmaxf(hi, 0.0f));
}

static constexpr int C = 16;
static constexpr int TPB = 256;

// Folded parameters: staged in a __device__ global by the fold kernel, then
// memcpy'd into __constant__ so the main kernel reads weights via the
// CONSTANT PORT (LDC/LDCU) instead of the l1tex/shared pipe.
struct FoldedParams {
    float WcT[C * C];   // [i*16 + o]   Wc^T, o contiguous (pairs adjacent)
    float WbT[C * C];   // [o*16 + q]   Wb^T, q contiguous
    float bc[C];        // folded bias: Wa@bt + ba
    float bb[C];
};

__device__ FoldedParams gStage;
__constant__ __align__(16) FoldedParams cP;

__global__ void fold_kernel(const float* __restrict__ Wt,
                            const float* __restrict__ bt,
                            const float* __restrict__ Wa,
                            const float* __restrict__ ba,
                            const float* __restrict__ Wb,
                            const float* __restrict__ bb)
{
    const int t = threadIdx.x;           // 256 threads
    const int o = t & 15;
    const int i = t >> 4;
    float acc = 0.0f;
#pragma unroll
    for (int m = 0; m < C; m++)
        acc += Wa[o * C + m] * Wt[m * C + i];
    gStage.WcT[i * C + o] = acc;                       // transposed
    gStage.WbT[t] = Wb[(t & 15) * C + (t >> 4)];       // WbT[o*16+q] = Wb[q][o]
    if (t < C) {
        float b = ba[t];
#pragma unroll
        for (int m = 0; m < C; m++)
            b += Wa[t * C + m] * bt[m];
        gStage.bc[t] = b;
        gStage.bb[t] = bb[t];
    }
}

// Main kernel: 4 rows/thread, weight-pair f32x2 scheme (R9), weights from
// __constant__ -> no smem, no __syncthreads, l1tex carries only LDG/STG.
__global__ __launch_bounds__(TPB, 2)
void dmasif_fused_kernel(const float* __restrict__ feat,
                         float* __restrict__ out,
                         long long n)
{
    const int t = threadIdx.x;
    const long long base = ((long long)blockIdx.x * TPB + t) * 4;
    if (base >= n) return;

    if (base + 4 > n) {
        // ---- scalar tail path (dead for N%4==0, kept for safety) ----
        for (int r = 0; r < 4; r++) {
            const long long row = base + r;
            if (row >= n) break;
            float h[C];
#pragma unroll
            for (int q = 0; q < C; q++) {
                float a = cP.bc[q];
                for (int i = 0; i < C; i++)
                    a += feat[row * C + i] * cP.WcT[i * C + q];
                h[q] = fmaxf(a, 0.0f);
            }
#pragma unroll
            for (int q = 0; q < C; q++) {
                float a = cP.bb[q];
                for (int o = 0; o < C; o++)
                    a += h[o] * cP.WbT[o * C + q];
                out[row * C + q] = a;
            }
        }
        return;
    }

    // ================= main path: 4 full rows =================
    // GEMM1 accumulators: acc[r][p] = (h[r][2p], h[r][2p+1])
    ull acc[4][8];
    {
#pragma unroll
        for (int p = 0; p < 8; p++) {
            const ull bp = *reinterpret_cast<const ull*>(&cP.bc[2 * p]);
#pragma unroll
            for (int r = 0; r < 4; r++) acc[r][p] = bp;
        }
    }

    const float4* f4 = reinterpret_cast<const float4*>(feat + base * C);
#pragma unroll
    for (int ic = 0; ic < 4; ic++) {
        const float4 g0 = f4[0 * 4 + ic];
        const float4 g1 = f4[1 * 4 + ic];
        const float4 g2 = f4[2 * 4 + ic];
        const float4 g3 = f4[3 * 4 + ic];
        float e0v[4] = {g0.x, g0.y, g0.z, g0.w};
        float e1v[4] = {g1.x, g1.y, g1.z, g1.w};
        float e2v[4] = {g2.x, g2.y, g2.z, g2.w};
        float e3v[4] = {g3.x, g3.y, g3.z, g3.w};
#pragma unroll
        for (int ii = 0; ii < 4; ii++) {
            const int i = ic * 4 + ii;
            // 16 weights for this i: 8 (o,o+1) pairs = 4 x ld.const.v2.u64
            const ulonglong2 wA = *reinterpret_cast<const ulonglong2*>(&cP.WcT[i * C + 0]);
            const ulonglong2 wB = *reinterpret_cast<const ulonglong2*>(&cP.WcT[i * C + 4]);
            const ulonglong2 wC = *reinterpret_cast<const ulonglong2*>(&cP.WcT[i * C + 8]);
            const ulonglong2 wD = *reinterpret_cast<const ulonglong2*>(&cP.WcT[i * C + 12]);
            const ull d0 = pack2(e0v[ii], e0v[ii]);
            const ull d1 = pack2(e1v[ii], e1v[ii]);
            const ull d2 = pack2(e2v[ii], e2v[ii]);
            const ull d3 = pack2(e3v[ii], e3v[ii]);
            acc[0][0] = ffma2(d0, wA.x, acc[0][0]); acc[0][1] = ffma2(d0, wA.y, acc[0][1]);
            acc[0][2] = ffma2(d0, wB.x, acc[0][2]); acc[0][3] = ffma2(d0, wB.y, acc[0][3]);
            acc[0][4] = ffma2(d0, wC.x, acc[0][4]); acc[0][5] = ffma2(d0, wC.y, acc[0][5]);
            acc[0][6] = ffma2(d0, wD.x, acc[0][6]); acc[0][7] = ffma2(d0, wD.y, acc[0][7]);
            acc[1][0] = ffma2(d1, wA.x, acc[1][0]); acc[1][1] = ffma2(d1, wA.y, acc[1][1]);
            acc[1][2] = ffma2(d1, wB.x, acc[1][2]); acc[1][3] = ffma2(d1, wB.y, acc[1][3]);
            acc[1][4] = ffma2(d1, wC.x, acc[1][4]); acc[1][5] = ffma2(d1, wC.y, acc[1][5]);
            acc[1][6] = ffma2(d1, wD.x, acc[1][6]); acc[1][7] = ffma2(d1, wD.y, acc[1][7]);
            acc[2][0] = ffma2(d2, wA.x, acc[2][0]); acc[2][1] = ffma2(d2, wA.y, acc[2][1]);
            acc[2][2] = ffma2(d2, wB.x, acc[2][2]); acc[2][3] = ffma2(d2, wB.y, acc[2][3]);
            acc[2][4] = ffma2(d2, wC.x, acc[2][4]); acc[2][5] = ffma2(d2, wC.y, acc[2][5]);
            acc[2][6] = ffma2(d2, wD.x, acc[2][6]); acc[2][7] = ffma2(d2, wD.y, acc[2][7]);
            acc[3][0] = ffma2(d3, wA.x, acc[3][0]); acc[3][1] = ffma2(d3, wA.y, acc[3][1]);
            acc[3][2] = ffma2(d3, wB.x, acc[3][2]); acc[3][3] = ffma2(d3, wB.y, acc[3][3]);
            acc[3][4] = ffma2(d3, wC.x, acc[3][4]); acc[3][5] = ffma2(d3, wC.y, acc[3][5]);
            acc[3][6] = ffma2(d3, wD.x, acc[3][6]); acc[3][7] = ffma2(d3, wD.y, acc[3][7]);
        }
    }

#pragma unroll
    for (int r = 0; r < 4; r++)
#pragma unroll
        for (int p = 0; p < 8; p++) acc[r][p] = relu2(acc[r][p]);

    // ---- GEMM2 in two q-halves to bound register pressure ----
    float* outp = out + base * C;
#pragma unroll
    for (int half = 0; half < 2; half++) {
        ull a2[4][4];  // q-pairs for this half
        {
#pragma unroll
            for (int pp = 0; pp < 4; pp++) {
                const ull bp = *reinterpret_cast<const ull*>(&cP.bb[half * 8 + 2 * pp]);
#pragma unroll
                for (int r = 0; r < 4; r++) a2[r][pp] = bp;
            }
        }
#pragma unroll
        for (int o = 0; o < C; o++) {
            const ulonglong2 wA = *reinterpret_cast<const ulonglong2*>(&cP.WbT[o * C + half * 8 + 0]);
            const ulonglong2 wB = *reinterpret_cast<const ulonglong2*>(&cP.WbT[o * C + half * 8 + 4]);
#pragma unroll
            for (int r = 0; r < 4; r++) {
                float hlo, hhi;
                unpack2(acc[r][o >> 1], hlo, hhi);
                const float hs = (o & 1) ? hhi : hlo;
                const ull hd = pack2(hs, hs);
                a2[r][0] = ffma2(hd, wA.x, a2[r][0]);
                a2[r][1] = ffma2(hd, wA.y, a2[r][1]);
                a2[r][2] = ffma2(hd, wB.x, a2[r][2]);
                a2[r][3] = ffma2(hd, wB.y, a2[r][3]);
            }
        }
        float4* g4 = reinterpret_cast<float4*>(outp + half * 8);
#pragma unroll
        for (int r = 0; r < 4; r++) {
            float v0, v1, v2, v3, v4, v5, v6, v7;
            unpack2(a2[r][0], v0, v1);
            unpack2(a2[r][1], v2, v3);
            unpack2(a2[r][2], v4, v5);
            unpack2(a2[r][3], v6, v7);
            g4[r * 4 + 0] = make_float4(v0, v1, v2, v3);
            g4[r * 4 + 1] = make_float4(v4, v5, v6, v7);
        }
    }
}

extern "C" void kernel_launch(void* const* d_in, const int* in_sizes, int n_in,
                              void* d_out, int out_size)
{
    // metadata order: features, points, nuv, Wt, bt, Wa, ba, Wb, bb, ranges
    const float* feat = (const float*)d_in[0];
    const float* Wt   = (const float*)d_in[3];
    const float* bt   = (const float*)d_in[4];
    const float* Wa   = (const float*)d_in[5];
    const float* ba   = (const float*)d_in[6];
    const float* Wb   = (const float*)d_in[7];
    const float* bb   = (const float*)d_in[8];
    float* out = (float*)d_out;

    const long long n = (long long)in_sizes[0] / C;
    const long long quads = (n + 3) / 4;
    const int blocks = (int)((quads + TPB - 1) / TPB);

    // 1) fold weights on device into the staging struct
    fold_kernel<<<1, 256>>>(Wt, bt, Wa, ba, Wb, bb);

    // 2) stage -> __constant__ (async D2D memcpy node; graph-capturable)
    void* stage_ptr = nullptr;
    cudaGetSymbolAddress(&stage_ptr, gStage);
    cudaMemcpyToSymbolAsync(cP, stage_ptr, sizeof(FoldedParams), 0,
                            cudaMemcpyDeviceToDevice, 0);

    // 3) main fused kernel reading weights via the constant port
    dmasif_fused_kernel<<<blocks, TPB>>>(feat, out, n);
}

// round 11
// speedup vs baseline: 1.6486x; 1.1622x over previous
#include <cuda_runtime.h>
#include <cuda_bf16.h>
#include <cstdint>

typedef unsigned long long ull;

// ---------------- f32x2 packed helpers (Blackwell) ----------------
__device__ __forceinline__ ull ffma2(ull a, ull b, ull c) {
    ull d;
    asm("fma.rn.f32x2 %0, %1, %2, %3;" : "=l"(d) : "l"(a), "l"(b), "l"(c));
    return d;
}
__device__ __forceinline__ ull pack2(float lo, float hi) {
    ull r;
    asm("mov.b64 %0, {%1, %2};" : "=l"(r) : "f"(lo), "f"(hi));
    return r;
}
__device__ __forceinline__ void unpack2(ull v, float& lo, float& hi) {
    asm("mov.b64 {%0, %1}, %2;" : "=f"(lo), "=f"(hi) : "l"(v));
}
__device__ __forceinline__ ull relu2(ull v) {
    float lo, hi;
    unpack2(v, lo, hi);
    return pack2(fmaxf(lo, 0.0f), fmaxf(hi, 0.0f));
}

static constexpr int C = 16;
static constexpr int TPB = 192;           // 192 threads * 4 rows = 768-row tile
static constexpr int TILE_ROWS = TPB * 4; // 768
static constexpr int TILE_F4 = TILE_ROWS * 4; // 3072 float4 = 48KB

// Swizzle on float4 index: XOR low 3 bits with bits [4:7).
// Conflict-free (optimal 4 phases) for BOTH the coalesced k*TPB+tid pattern
// and the row-owner 16*tid+j pattern.
__device__ __forceinline__ int sw(int L) { return L ^ ((L >> 4) & 7); }

// Folded parameters in __constant__ -> weight reads on the constant port.
struct FoldedParams {
    float WcT[C * C];   // [i*16 + o]   Wc^T, o contiguous (pairs adjacent)
    float WbT[C * C];   // [o*16 + q]   Wb^T, q contiguous
    float bc[C];        // folded bias: Wa@bt + ba
    float bb[C];
};

__device__ FoldedParams gStage;
__constant__ __align__(16) FoldedParams cP;

__global__ void fold_kernel(const float* __restrict__ Wt,
                            const float* __restrict__ bt,
                            const float* __restrict__ Wa,
                            const float* __restrict__ ba,
                            const float* __restrict__ Wb,
                            const float* __restrict__ bb)
{
    const int t = threadIdx.x;           // 256 threads
    const int o = t & 15;
    const int i = t >> 4;
    float acc = 0.0f;
#pragma unroll
    for (int m = 0; m < C; m++)
        acc += Wa[o * C + m] * Wt[m * C + i];
    gStage.WcT[i * C + o] = acc;
    gStage.WbT[t] = Wb[(t & 15) * C + (t >> 4)];
    if (t < C) {
        float b = ba[t];
#pragma unroll
        for (int m = 0; m < C; m++)
            b += Wa[t * C + m] * bt[m];
        gStage.bc[t] = b;
        gStage.bb[t] = bb[t];
    }
}

__global__ __launch_bounds__(TPB, 2)
void dmasif_fused_kernel(const float* __restrict__ feat,
                         float* __restrict__ out,
                         long long n)
{
    __shared__ float4 sT[TILE_F4];    // 48KB, features then reused for outputs

    const int tid = threadIdx.x;
    const long long tileBase = (long long)blockIdx.x * TILE_ROWS;
    const bool fullTile = (tileBase + TILE_ROWS <= n);

    if (!fullTile) {
        // ---------- partial-tile path: direct (uncoalesced) global access ----------
        const long long base = tileBase + (long long)tid * 4;
        if (base >= n) return;
        for (int r = 0; r < 4; r++) {
            const long long row = base + r;
            if (row >= n) break;
            float h[C];
#pragma unroll
            for (int q = 0; q < C; q++) {
                float a = cP.bc[q];
                for (int i = 0; i < C; i++)
                    a += feat[row * C + i] * cP.WcT[i * C + q];
                h[q] = fmaxf(a, 0.0f);
            }
#pragma unroll
            for (int q = 0; q < C; q++) {
                float a = cP.bb[q];
                for (int o = 0; o < C; o++)
                    a += h[o] * cP.WbT[o * C + q];
                out[row * C + q] = a;
            }
        }
        return;
    }

    // ================= full tile =================
    // 1) coalesced load -> swizzled smem
    {
        const float4* gf4 = reinterpret_cast<const float4*>(feat + tileBase * C);
#pragma unroll
        for (int k = 0; k < 16; k++) {
            const int L = k * TPB + tid;
            sT[sw(L)] = gf4[L];
        }
    }
    __syncthreads();

    // 2) read own 4 rows from smem (conflict-free)
    float4 f[16];
#pragma unroll
    for (int j = 0; j < 16; j++)
        f[j] = sT[sw(16 * tid + j)];

    // ---- GEMM1 + ReLU: acc[r][p] = (h[r][2p], h[r][2p+1]) ----
    ull acc[4][8];
#pragma unroll
    for (int p = 0; p < 8; p++) {
        const ull bp = *reinterpret_cast<const ull*>(&cP.bc[2 * p]);
#pragma unroll
        for (int r = 0; r < 4; r++) acc[r][p] = bp;
    }

#pragma unroll
    for (int ic = 0; ic < 4; ic++) {
        const float4 g0 = f[0 * 4 + ic];
        const float4 g1 = f[1 * 4 + ic];
        const float4 g2 = f[2 * 4 + ic];
        const float4 g3 = f[3 * 4 + ic];
        float e0v[4] = {g0.x, g0.y, g0.z, g0.w};
        float e1v[4] = {g1.x, g1.y, g1.z, g1.w};
        float e2v[4] = {g2.x, g2.y, g2.z, g2.w};
        float e3v[4] = {g3.x, g3.y, g3.z, g3.w};
#pragma unroll
        for (int ii = 0; ii < 4; ii++) {
            const int i = ic * 4 + ii;
            const ulonglong2 wA = *reinterpret_cast<const ulonglong2*>(&cP.WcT[i * C + 0]);
            const ulonglong2 wB = *reinterpret_cast<const ulonglong2*>(&cP.WcT[i * C + 4]);
            const ulonglong2 wC = *reinterpret_cast<const ulonglong2*>(&cP.WcT[i * C + 8]);
            const ulonglong2 wD = *reinterpret_cast<const ulonglong2*>(&cP.WcT[i * C + 12]);
            const ull d0 = pack2(e0v[ii], e0v[ii]);
            const ull d1 = pack2(e1v[ii], e1v[ii]);
            const ull d2 = pack2(e2v[ii], e2v[ii]);
            const ull d3 = pack2(e3v[ii], e3v[ii]);
            acc[0][0] = ffma2(d0, wA.x, acc[0][0]); acc[0][1] = ffma2(d0, wA.y, acc[0][1]);
            acc[0][2] = ffma2(d0, wB.x, acc[0][2]); acc[0][3] = ffma2(d0, wB.y, acc[0][3]);
            acc[0][4] = ffma2(d0, wC.x, acc[0][4]); acc[0][5] = ffma2(d0, wC.y, acc[0][5]);
            acc[0][6] = ffma2(d0, wD.x, acc[0][6]); acc[0][7] = ffma2(d0, wD.y, acc[0][7]);
            acc[1][0] = ffma2(d1, wA.x, acc[1][0]); acc[1][1] = ffma2(d1, wA.y, acc[1][1]);
            acc[1][2] = ffma2(d1, wB.x, acc[1][2]); acc[1][3] = ffma2(d1, wB.y, acc[1][3]);
            acc[1][4] = ffma2(d1, wC.x, acc[1][4]); acc[1][5] = ffma2(d1, wC.y, acc[1][5]);
            acc[1][6] = ffma2(d1, wD.x, acc[1][6]); acc[1][7] = ffma2(d1, wD.y, acc[1][7]);
            acc[2][0] = ffma2(d2, wA.x, acc[2][0]); acc[2][1] = ffma2(d2, wA.y, acc[2][1]);
            acc[2][2] = ffma2(d2, wB.x, acc[2][2]); acc[2][3] = ffma2(d2, wB.y, acc[2][3]);
            acc[2][4] = ffma2(d2, wC.x, acc[2][4]); acc[2][5] = ffma2(d2, wC.y, acc[2][5]);
            acc[2][6] = ffma2(d2, wD.x, acc[2][6]); acc[2][7] = ffma2(d2, wD.y, acc[2][7]);
            acc[3][0] = ffma2(d3, wA.x, acc[3][0]); acc[3][1] = ffma2(d3, wA.y, acc[3][1]);
            acc[3][2] = ffma2(d3, wB.x, acc[3][2]); acc[3][3] = ffma2(d3, wB.y, acc[3][3]);
            acc[3][4] = ffma2(d3, wC.x, acc[3][4]); acc[3][5] = ffma2(d3, wC.y, acc[3][5]);
            acc[3][6] = ffma2(d3, wD.x, acc[3][6]); acc[3][7] = ffma2(d3, wD.y, acc[3][7]);
        }
    }

#pragma unroll
    for (int r = 0; r < 4; r++)
#pragma unroll
        for (int p = 0; p < 8; p++) acc[r][p] = relu2(acc[r][p]);

    // ---- GEMM2: results written into OWN smem slots (no sync needed; only
    // this thread ever read slots sw(16*tid + j)) ----
#pragma unroll
    for (int half = 0; half < 2; half++) {
        ull a2[4][4];
#pragma unroll
        for (int pp = 0; pp < 4; pp++) {
            const ull bp = *reinterpret_cast<const ull*>(&cP.bb[half * 8 + 2 * pp]);
#pragma unroll
            for (int r = 0; r < 4; r++) a2[r][pp] = bp;
        }
#pragma unroll
        for (int o = 0; o < C; o++) {
            const ulonglong2 wA = *reinterpret_cast<const ulonglong2*>(&cP.WbT[o * C + half * 8 + 0]);
            const ulonglong2 wB = *reinterpret_cast<const ulonglong2*>(&cP.WbT[o * C + half * 8 + 4]);
#pragma unroll
            for (int r = 0; r < 4; r++) {
                float hlo, hhi;
                unpack2(acc[r][o >> 1], hlo, hhi);
                const float hs = (o & 1) ? hhi : hlo;
                const ull hd = pack2(hs, hs);
                a2[r][0] = ffma2(hd, wA.x, a2[r][0]);
                a2[r][1] = ffma2(hd, wA.y, a2[r][1]);
                a2[r][2] = ffma2(hd, wB.x, a2[r][2]);
                a2[r][3] = ffma2(hd, wB.y, a2[r][3]);
            }
        }
#pragma unroll
        for (int r = 0; r < 4; r++) {
            float v0, v1, v2, v3, v4, v5, v6, v7;
            unpack2(a2[r][0], v0, v1);
            unpack2(a2[r][1], v2, v3);
            unpack2(a2[r][2], v4, v5);
            unpack2(a2[r][3], v6, v7);
            sT[sw(16 * tid + r * 4 + half * 2 + 0)] = make_float4(v0, v1, v2, v3);
            sT[sw(16 * tid + r * 4 + half * 2 + 1)] = make_float4(v4, v5, v6, v7);
        }
    }
    __syncthreads();

    // 3) coalesced store from swizzled smem
    {
        float4* go4 = reinterpret_cast<float4*>(out + tileBase * C);
#pragma unroll
        for (int k = 0; k < 16; k++) {
            const int L = k * TPB + tid;
            go4[L] = sT[sw(L)];
        }
    }
}

extern "C" void kernel_launch(void* const* d_in, const int* in_sizes, int n_in,
                              void* d_out, int out_size)
{
    // metadata order: features, points, nuv, Wt, bt, Wa, ba, Wb, bb, ranges
    const float* feat = (const float*)d_in[0];
    const float* Wt   = (const float*)d_in[3];
    const float* bt   = (const float*)d_in[4];
    const float* Wa   = (const float*)d_in[5];
    const float* ba   = (const float*)d_in[6];
    const float* Wb   = (const float*)d_in[7];
    const float* bb   = (const float*)d_in[8];
    float* out = (float*)d_out;

    const long long n = (long long)in_sizes[0] / C;
    const int blocks = (int)((n + TILE_ROWS - 1) / TILE_ROWS);

    fold_kernel<<<1, 256>>>(Wt, bt, Wa, ba, Wb, bb);

    void* stage_ptr = nullptr;
    cudaGetSymbolAddress(&stage_ptr, gStage);
    cudaMemcpyToSymbolAsync(cP, stage_ptr, sizeof(FoldedParams), 0,
                            cudaMemcpyDeviceToDevice, 0);

    dmasif_fused_kernel<<<blocks, TPB>>>(feat, out, n);
}

// round 12
// speedup vs baseline: 1.9072x; 1.1568x over previous
#include <cuda_runtime.h>
#include <cuda_bf16.h>
#include <cstdint>

typedef unsigned long long ull;

// ---------------- f32x2 packed helpers (Blackwell) ----------------
__device__ __forceinline__ ull ffma2(ull a, ull b, ull c) {
    ull d;
    asm("fma.rn.f32x2 %0, %1, %2, %3;" : "=l"(d) : "l"(a), "l"(b), "l"(c));
    return d;
}
__device__ __forceinline__ ull pack2(float lo, float hi) {
    ull r;
    asm("mov.b64 %0, {%1, %2};" : "=l"(r) : "f"(lo), "f"(hi));
    return r;
}
__device__ __forceinline__ void unpack2(ull v, float& lo, float& hi) {
    asm("mov.b64 {%0, %1}, %2;" : "=f"(lo), "=f"(hi) : "l"(v));
}
__device__ __forceinline__ ull relu2(ull v) {
    float lo, hi;
    unpack2(v, lo, hi);
    return pack2(fmaxf(lo, 0.0f), fmaxf(hi, 0.0f));
}

static constexpr int C = 16;
static constexpr int TPB = 128;               // 128 threads * 4 rows = 512-row tile
static constexpr int TILE_ROWS = TPB * 4;     // 512
static constexpr int TILE_F4 = TILE_ROWS * 4; // 2048 float4 = 32KB

// Swizzle on float4 index: XOR low 3 bits with bits [4:7).
// Conflict-free for both the coalesced k*TPB+tid pattern and 16*tid+j.
__device__ __forceinline__ int sw(int L) { return L ^ ((L >> 4) & 7); }

// Folded parameters in __constant__ -> weight reads on the constant port.
struct FoldedParams {
    float WcT[C * C];   // [i*16 + o]   Wc^T, o contiguous (pairs adjacent)
    float WbT[C * C];   // [o*16 + q]   Wb^T, q contiguous
    float bc[C];        // folded bias: Wa@bt + ba
    float bb[C];
};

__device__ FoldedParams gStage;
__constant__ __align__(16) FoldedParams cP;

__global__ void fold_kernel(const float* __restrict__ Wt,
                            const float* __restrict__ bt,
                            const float* __restrict__ Wa,
                            const float* __restrict__ ba,
                            const float* __restrict__ Wb,
                            const float* __restrict__ bb)
{
    const int t = threadIdx.x;           // 256 threads
    const int o = t & 15;
    const int i = t >> 4;
    float acc = 0.0f;
#pragma unroll
    for (int m = 0; m < C; m++)
        acc += Wa[o * C + m] * Wt[m * C + i];
    gStage.WcT[i * C + o] = acc;
    gStage.WbT[t] = Wb[(t & 15) * C + (t >> 4)];
    if (t < C) {
        float b = ba[t];
#pragma unroll
        for (int m = 0; m < C; m++)
            b += Wa[t * C + m] * bt[m];
        gStage.bc[t] = b;
        gStage.bb[t] = bb[t];
    }
}

__global__ __launch_bounds__(TPB, 4)
void dmasif_fused_kernel(const float* __restrict__ feat,
                         float* __restrict__ out,
                         long long n)
{
    __shared__ float4 sT[TILE_F4];    // 32KB, features then reused for outputs

    const int tid = threadIdx.x;
    const long long tileBase = (long long)blockIdx.x * TILE_ROWS;
    const bool fullTile = (tileBase + TILE_ROWS <= n);

    if (!fullTile) {
        // ---------- partial-tile path (last block only) ----------
        const long long base = tileBase + (long long)tid * 4;
        if (base >= n) return;
        for (int r = 0; r < 4; r++) {
            const long long row = base + r;
            if (row >= n) break;
            float h[C];
#pragma unroll
            for (int q = 0; q < C; q++) {
                float a = cP.bc[q];
                for (int i = 0; i < C; i++)
                    a += feat[row * C + i] * cP.WcT[i * C + q];
                h[q] = fmaxf(a, 0.0f);
            }
#pragma unroll
            for (int q = 0; q < C; q++) {
                float a = cP.bb[q];
                for (int o = 0; o < C; o++)
                    a += h[o] * cP.WbT[o * C + q];
                out[row * C + q] = a;
            }
        }
        return;
    }

    // ================= full tile =================
    // 1) coalesced load -> swizzled smem
    {
        const float4* gf4 = reinterpret_cast<const float4*>(feat + tileBase * C);
#pragma unroll
        for (int k = 0; k < 16; k++) {
            const int L = k * TPB + tid;
            sT[sw(L)] = gf4[L];
        }
    }
    __syncthreads();

    // ---- GEMM1 + ReLU: acc[r][p] = (h[r][2p], h[r][2p+1]) ----
    // Feature float4s are read from smem PER ic-CHUNK (4 live at a time)
    // to keep the register peak low enough for 4 CTAs/SM.
    ull acc[4][8];
#pragma unroll
    for (int p = 0; p < 8; p++) {
        const ull bp = *reinterpret_cast<const ull*>(&cP.bc[2 * p]);
#pragma unroll
        for (int r = 0; r < 4; r++) acc[r][p] = bp;
    }

#pragma unroll
    for (int ic = 0; ic < 4; ic++) {
        const float4 g0 = sT[sw(16 * tid + 0 * 4 + ic)];
        const float4 g1 = sT[sw(16 * tid + 1 * 4 + ic)];
        const float4 g2 = sT[sw(16 * tid + 2 * 4 + ic)];
        const float4 g3 = sT[sw(16 * tid + 3 * 4 + ic)];
        float e0v[4] = {g0.x, g0.y, g0.z, g0.w};
        float e1v[4] = {g1.x, g1.y, g1.z, g1.w};
        float e2v[4] = {g2.x, g2.y, g2.z, g2.w};
        float e3v[4] = {g3.x, g3.y, g3.z, g3.w};
#pragma unroll
        for (int ii = 0; ii < 4; ii++) {
            const int i = ic * 4 + ii;
            const ulonglong2 wA = *reinterpret_cast<const ulonglong2*>(&cP.WcT[i * C + 0]);
            const ulonglong2 wB = *reinterpret_cast<const ulonglong2*>(&cP.WcT[i * C + 4]);
            const ulonglong2 wC = *reinterpret_cast<const ulonglong2*>(&cP.WcT[i * C + 8]);
            const ulonglong2 wD = *reinterpret_cast<const ulonglong2*>(&cP.WcT[i * C + 12]);
            const ull d0 = pack2(e0v[ii], e0v[ii]);
            const ull d1 = pack2(e1v[ii], e1v[ii]);
            const ull d2 = pack2(e2v[ii], e2v[ii]);
            const ull d3 = pack2(e3v[ii], e3v[ii]);
            acc[0][0] = ffma2(d0, wA.x, acc[0][0]); acc[0][1] = ffma2(d0, wA.y, acc[0][1]);
            acc[0][2] = ffma2(d0, wB.x, acc[0][2]); acc[0][3] = ffma2(d0, wB.y, acc[0][3]);
            acc[0][4] = ffma2(d0, wC.x, acc[0][4]); acc[0][5] = ffma2(d0, wC.y, acc[0][5]);
            acc[0][6] = ffma2(d0, wD.x, acc[0][6]); acc[0][7] = ffma2(d0, wD.y, acc[0][7]);
            acc[1][0] = ffma2(d1, wA.x, acc[1][0]); acc[1][1] = ffma2(d1, wA.y, acc[1][1]);
            acc[1][2] = ffma2(d1, wB.x, acc[1][2]); acc[1][3] = ffma2(d1, wB.y, acc[1][3]);
            acc[1][4] = ffma2(d1, wC.x, acc[1][4]); acc[1][5] = ffma2(d1, wC.y, acc[1][5]);
            acc[1][6] = ffma2(d1, wD.x, acc[1][6]); acc[1][7] = ffma2(d1, wD.y, acc[1][7]);
            acc[2][0] = ffma2(d2, wA.x, acc[2][0]); acc[2][1] = ffma2(d2, wA.y, acc[2][1]);
            acc[2][2] = ffma2(d2, wB.x, acc[2][2]); acc[2][3] = ffma2(d2, wB.y, acc[2][3]);
            acc[2][4] = ffma2(d2, wC.x, acc[2][4]); acc[2][5] = ffma2(d2, wC.y, acc[2][5]);
            acc[2][6] = ffma2(d2, wD.x, acc[2][6]); acc[2][7] = ffma2(d2, wD.y, acc[2][7]);
            acc[3][0] = ffma2(d3, wA.x, acc[3][0]); acc[3][1] = ffma2(d3, wA.y, acc[3][1]);
            acc[3][2] = ffma2(d3, wB.x, acc[3][2]); acc[3][3] = ffma2(d3, wB.y, acc[3][3]);
            acc[3][4] = ffma2(d3, wC.x, acc[3][4]); acc[3][5] = ffma2(d3, wC.y, acc[3][5]);
            acc[3][6] = ffma2(d3, wD.x, acc[3][6]); acc[3][7] = ffma2(d3, wD.y, acc[3][7]);
        }
    }

#pragma unroll
    for (int r = 0; r < 4; r++)
#pragma unroll
        for (int p = 0; p < 8; p++) acc[r][p] = relu2(acc[r][p]);

    // ---- GEMM2: results written into OWN smem slots (no extra sync) ----
#pragma unroll
    for (int half = 0; half < 2; half++) {
        ull a2[4][4];
#pragma unroll
        for (int pp = 0; pp < 4; pp++) {
            const ull bp = *reinterpret_cast<const ull*>(&cP.bb[half * 8 + 2 * pp]);
#pragma unroll
            for (int r = 0; r < 4; r++) a2[r][pp] = bp;
        }
#pragma unroll
        for (int o = 0; o < C; o++) {
            const ulonglong2 wA = *reinterpret_cast<const ulonglong2*>(&cP.WbT[o * C + half * 8 + 0]);
            const ulonglong2 wB = *reinterpret_cast<const ulonglong2*>(&cP.WbT[o * C + half * 8 + 4]);
#pragma unroll
            for (int r = 0; r < 4; r++) {
                float hlo, hhi;
                unpack2(acc[r][o >> 1], hlo, hhi);
                const float hs = (o & 1) ? hhi : hlo;
                const ull hd = pack2(hs, hs);
                a2[r][0] = ffma2(hd, wA.x, a2[r][0]);
                a2[r][1] = ffma2(hd, wA.y, a2[r][1]);
                a2[r][2] = ffma2(hd, wB.x, a2[r][2]);
                a2[r][3] = ffma2(hd, wB.y, a2[r][3]);
            }
        }
#pragma unroll
        for (int r = 0; r < 4; r++) {
            float v0, v1, v2, v3, v4, v5, v6, v7;
            unpack2(a2[r][0], v0, v1);
            unpack2(a2[r][1], v2, v3);
            unpack2(a2[r][2], v4, v5);
            unpack2(a2[r][3], v6, v7);
            sT[sw(16 * tid + r * 4 + half * 2 + 0)] = make_float4(v0, v1, v2, v3);
            sT[sw(16 * tid + r * 4 + half * 2 + 1)] = make_float4(v4, v5, v6, v7);
        }
    }
    __syncthreads();

    // 3) coalesced store from swizzled smem
    {
        float4* go4 = reinterpret_cast<float4*>(out + tileBase * C);
#pragma unroll
        for (int k = 0; k < 16; k++) {
            const int L = k * TPB + tid;
            go4[L] = sT[sw(L)];
        }
    }
}

extern "C" void kernel_launch(void* const* d_in, const int* in_sizes, int n_in,
                              void* d_out, int out_size)
{
    // metadata order: features, points, nuv, Wt, bt, Wa, ba, Wb, bb, ranges
    const float* feat = (const float*)d_in[0];
    const float* Wt   = (const float*)d_in[3];
    const float* bt   = (const float*)d_in[4];
    const float* Wa   = (const float*)d_in[5];
    const float* ba   = (const float*)d_in[6];
    const float* Wb   = (const float*)d_in[7];
    const float* bb   = (const float*)d_in[8];
    float* out = (float*)d_out;

    const long long n = (long long)in_sizes[0] / C;
    const int blocks = (int)((n + TILE_ROWS - 1) / TILE_ROWS);

    fold_kernel<<<1, 256>>>(Wt, bt, Wa, ba, Wb, bb);

    void* stage_ptr = nullptr;
    cudaGetSymbolAddress(&stage_ptr, gStage);
    cudaMemcpyToSymbolAsync(cP, stage_ptr, sizeof(FoldedParams), 0,
                            cudaMemcpyDeviceToDevice, 0);

    dmasif_fused_kernel<<<blocks, TPB>>>(feat, out, n);
}

// round 13
// speedup vs baseline: 2.2804x; 1.1957x over previous
#include <cuda_runtime.h>
#include <cuda_bf16.h>
#include <cstdint>

typedef unsigned long long ull;

// ---------------- f32x2 packed helpers (Blackwell) ----------------
__device__ __forceinline__ ull ffma2(ull a, ull b, ull c) {
    ull d;
    asm("fma.rn.f32x2 %0, %1, %2, %3;" : "=l"(d) : "l"(a), "l"(b), "l"(c));
    return d;
}
__device__ __forceinline__ ull pack2(float lo, float hi) {
    ull r;
    asm("mov.b64 %0, {%1, %2};" : "=l"(r) : "f"(lo), "f"(hi));
    return r;
}
__device__ __forceinline__ void unpack2(ull v, float& lo, float& hi) {
    asm("mov.b64 {%0, %1}, %2;" : "=f"(lo), "=f"(hi) : "l"(v));
}
__device__ __forceinline__ ull relu2(ull v) {
    float lo, hi;
    unpack2(v, lo, hi);
    return pack2(fmaxf(lo, 0.0f), fmaxf(hi, 0.0f));
}

static constexpr int C = 16;
static constexpr int TPB = 128;               // 128 threads * 2 rows = 256-row tile
static constexpr int ROWS = 2;                // rows per thread
static constexpr int TILE_ROWS = TPB * ROWS;  // 256
static constexpr int TILE_F4 = TILE_ROWS * 4; // 1024 float4 = 16KB

// Swizzle on float4 index: XOR low 3 bits with bits [4:7).
// Conflict-free for both the coalesced k*TPB+tid pattern and 8*tid+j.
__device__ __forceinline__ int sw(int L) { return L ^ ((L >> 4) & 7); }

// Folded parameters in __constant__ -> weight reads on the constant port.
struct FoldedParams {
    float WcT[C * C];   // [i*16 + o]   Wc^T, o contiguous (pairs adjacent)
    float WbT[C * C];   // [o*16 + q]   Wb^T, q contiguous
    float bc[C];        // folded bias: Wa@bt + ba
    float bb[C];
};

__device__ FoldedParams gStage;
__constant__ __align__(16) FoldedParams cP;

__global__ void fold_kernel(const float* __restrict__ Wt,
                            const float* __restrict__ bt,
                            const float* __restrict__ Wa,
                            const float* __restrict__ ba,
                            const float* __restrict__ Wb,
                            const float* __restrict__ bb)
{
    const int t = threadIdx.x;           // 256 threads
    const int o = t & 15;
    const int i = t >> 4;
    float acc = 0.0f;
#pragma unroll
    for (int m = 0; m < C; m++)
        acc += Wa[o * C + m] * Wt[m * C + i];
    gStage.WcT[i * C + o] = acc;
    gStage.WbT[t] = Wb[(t & 15) * C + (t >> 4)];
    if (t < C) {
        float b = ba[t];
#pragma unroll
        for (int m = 0; m < C; m++)
            b += Wa[t * C + m] * bt[m];
        gStage.bc[t] = b;
        gStage.bb[t] = bb[t];
    }
}

__global__ __launch_bounds__(TPB, 6)
void dmasif_fused_kernel(const float* __restrict__ feat,
                         float* __restrict__ out,
                         long long n)
{
    __shared__ float4 sT[TILE_F4];    // 16KB, features then reused for outputs

    const int tid = threadIdx.x;
    const long long tileBase = (long long)blockIdx.x * TILE_ROWS;
    const bool fullTile = (tileBase + TILE_ROWS <= n);

    if (!fullTile) {
        // ---------- partial-tile path (last block only; dead for N%256==0) ----------
        const long long base = tileBase + (long long)tid * ROWS;
        if (base >= n) return;
        for (int r = 0; r < ROWS; r++) {
            const long long row = base + r;
            if (row >= n) break;
            float h[C];
#pragma unroll
            for (int q = 0; q < C; q++) {
                float a = cP.bc[q];
                for (int i = 0; i < C; i++)
                    a += feat[row * C + i] * cP.WcT[i * C + q];
                h[q] = fmaxf(a, 0.0f);
            }
#pragma unroll
            for (int q = 0; q < C; q++) {
                float a = cP.bb[q];
                for (int o = 0; o < C; o++)
                    a += h[o] * cP.WbT[o * C + q];
                out[row * C + q] = a;
            }
        }
        return;
    }

    // ================= full tile =================
    // 1) coalesced load -> swizzled smem  (8 x float4 per thread)
    {
        const float4* gf4 = reinterpret_cast<const float4*>(feat + tileBase * C);
#pragma unroll
        for (int k = 0; k < 8; k++) {
            const int L = k * TPB + tid;
            sT[sw(L)] = gf4[L];
        }
    }
    __syncthreads();

    // ---- GEMM1 + ReLU: acc[r][p] = (h[r][2p], h[r][2p+1]) ----
    ull acc[ROWS][8];
#pragma unroll
    for (int p = 0; p < 8; p++) {
        const ull bp = *reinterpret_cast<const ull*>(&cP.bc[2 * p]);
#pragma unroll
        for (int r = 0; r < ROWS; r++) acc[r][p] = bp;
    }

#pragma unroll
    for (int ic = 0; ic < 4; ic++) {
        const float4 g0 = sT[sw(8 * tid + 0 * 4 + ic)];
        const float4 g1 = sT[sw(8 * tid + 1 * 4 + ic)];
        float e0v[4] = {g0.x, g0.y, g0.z, g0.w};
        float e1v[4] = {g1.x, g1.y, g1.z, g1.w};
#pragma unroll
        for (int ii = 0; ii < 4; ii++) {
            const int i = ic * 4 + ii;
            const ulonglong2 wA = *reinterpret_cast<const ulonglong2*>(&cP.WcT[i * C + 0]);
            const ulonglong2 wB = *reinterpret_cast<const ulonglong2*>(&cP.WcT[i * C + 4]);
            const ulonglong2 wC = *reinterpret_cast<const ulonglong2*>(&cP.WcT[i * C + 8]);
            const ulonglong2 wD = *reinterpret_cast<const ulonglong2*>(&cP.WcT[i * C + 12]);
            const ull d0 = pack2(e0v[ii], e0v[ii]);
            const ull d1 = pack2(e1v[ii], e1v[ii]);
            acc[0][0] = ffma2(d0, wA.x, acc[0][0]); acc[0][1] = ffma2(d0, wA.y, acc[0][1]);
            acc[0][2] = ffma2(d0, wB.x, acc[0][2]); acc[0][3] = ffma2(d0, wB.y, acc[0][3]);
            acc[0][4] = ffma2(d0, wC.x, acc[0][4]); acc[0][5] = ffma2(d0, wC.y, acc[0][5]);
            acc[0][6] = ffma2(d0, wD.x, acc[0][6]); acc[0][7] = ffma2(d0, wD.y, acc[0][7]);
            acc[1][0] = ffma2(d1, wA.x, acc[1][0]); acc[1][1] = ffma2(d1, wA.y, acc[1][1]);
            acc[1][2] = ffma2(d1, wB.x, acc[1][2]); acc[1][3] = ffma2(d1, wB.y, acc[1][3]);
            acc[1][4] = ffma2(d1, wC.x, acc[1][4]); acc[1][5] = ffma2(d1, wC.y, acc[1][5]);
            acc[1][6] = ffma2(d1, wD.x, acc[1][6]); acc[1][7] = ffma2(d1, wD.y, acc[1][7]);
        }
    }

#pragma unroll
    for (int r = 0; r < ROWS; r++)
#pragma unroll
        for (int p = 0; p < 8; p++) acc[r][p] = relu2(acc[r][p]);

    // ---- GEMM2: results written into OWN smem slots (no extra sync) ----
#pragma unroll
    for (int half = 0; half < 2; half++) {
        ull a2[ROWS][4];
#pragma unroll
        for (int pp = 0; pp < 4; pp++) {
            const ull bp = *reinterpret_cast<const ull*>(&cP.bb[half * 8 + 2 * pp]);
#pragma unroll
            for (int r = 0; r < ROWS; r++) a2[r][pp] = bp;
        }
#pragma unroll
        for (int o = 0; o < C; o++) {
            const ulonglong2 wA = *reinterpret_cast<const ulonglong2*>(&cP.WbT[o * C + half * 8 + 0]);
            const ulonglong2 wB = *reinterpret_cast<const ulonglong2*>(&cP.WbT[o * C + half * 8 + 4]);
#pragma unroll
            for (int r = 0; r < ROWS; r++) {
                float hlo, hhi;
                unpack2(acc[r][o >> 1], hlo, hhi);
                const float hs = (o & 1) ? hhi : hlo;
                const ull hd = pack2(hs, hs);
                a2[r][0] = ffma2(hd, wA.x, a2[r][0]);
                a2[r][1] = ffma2(hd, wA.y, a2[r][1]);
                a2[r][2] = ffma2(hd, wB.x, a2[r][2]);
                a2[r][3] = ffma2(hd, wB.y, a2[r][3]);
            }
        }
#pragma unroll
        for (int r = 0; r < ROWS; r++) {
            float v0, v1, v2, v3, v4, v5, v6, v7;
            unpack2(a2[r][0], v0, v1);
            unpack2(a2[r][1], v2, v3);
            unpack2(a2[r][2], v4, v5);
            unpack2(a2[r][3], v6, v7);
            sT[sw(8 * tid + r * 4 + half * 2 + 0)] = make_float4(v0, v1, v2, v3);
            sT[sw(8 * tid + r * 4 + half * 2 + 1)] = make_float4(v4, v5, v6, v7);
        }
    }
    __syncthreads();

    // 3) coalesced store from swizzled smem
    {
        float4* go4 = reinterpret_cast<float4*>(out + tileBase * C);
#pragma unroll
        for (int k = 0; k < 8; k++) {
            const int L = k * TPB + tid;
            go4[L] = sT[sw(L)];
        }
    }
}

extern "C" void kernel_launch(void* const* d_in, const int* in_sizes, int n_in,
                              void* d_out, int out_size)
{
    // metadata order: features, points, nuv, Wt, bt, Wa, ba, Wb, bb, ranges
    const float* feat = (const float*)d_in[0];
    const float* Wt   = (const float*)d_in[3];
    const float* bt   = (const float*)d_in[4];
    const float* Wa   = (const float*)d_in[5];
    const float* ba   = (const float*)d_in[6];
    const float* Wb   = (const float*)d_in[7];
    const float* bb   = (const float*)d_in[8];
    float* out = (float*)d_out;

    const long long n = (long long)in_sizes[0] / C;
    const int blocks = (int)((n + TILE_ROWS - 1) / TILE_ROWS);

    fold_kernel<<<1, 256>>>(Wt, bt, Wa, ba, Wb, bb);

    void* stage_ptr = nullptr;
    cudaGetSymbolAddress(&stage_ptr, gStage);
    cudaMemcpyToSymbolAsync(cP, stage_ptr, sizeof(FoldedParams), 0,
                            cudaMemcpyDeviceToDevice, 0);

    dmasif_fused_kernel<<<blocks, TPB>>>(feat, out, n);
}